// round 2
// baseline (speedup 1.0000x reference)
#include <cuda_runtime.h>
#include <math.h>

#define NN 100000
#define NE 3200000
#define DF 512
#define DH 64
#define NC 40

#define TM 256      // gemm1 row tile
#define KB 32       // gemm1 k chunk
#define SXS (TM+4)  // transposed x tile stride

// scratch (device globals: no allocation allowed)
__device__ int   g_is64;
__device__ float g_deg[NN];
__device__ float g_dinv[NN];
__device__ float g_h1[(size_t)NN*DH];
__device__ float g_agg1[(size_t)NN*DH];
__device__ float g_h2[(size_t)NN*NC];
__device__ float g_agg2[(size_t)NN*NC];

// ---------------- edge_index dtype detection --------------------------------
// If int64 (little-endian), words at odd indices are high words == 0
// (node ids in [0, 100000)). If int32, odd words are real ids, almost surely
// not all zero across 1024 samples.
__global__ void k_detect(const int* __restrict__ ei32) {
    __shared__ int nz;
    if (threadIdx.x == 0) nz = 0;
    __syncthreads();
    int local = 0;
    for (int i = threadIdx.x; i < 1024; i += blockDim.x)
        if (ei32[2*i + 1] != 0) local = 1;
    if (local) atomicOr(&nz, 1);
    __syncthreads();
    if (threadIdx.x == 0) g_is64 = (nz == 0) ? 1 : 0;
}

__device__ __forceinline__ int load_idx(const void* ei, size_t pos, int is64) {
    if (is64) return (int)((const long long*)ei)[pos];
    return ((const int*)ei)[pos];
}

// ---------------- degree / norm ----------------
__global__ void k_init_deg() {
    int i = blockIdx.x*blockDim.x + threadIdx.x;
    if (i < NN) g_deg[i] = 1.0f;   // self-loop weight 1
}

__global__ void k_accum_deg(const void* __restrict__ ei,
                            const float* __restrict__ ew) {
    int e = blockIdx.x*blockDim.x + threadIdx.x;
    if (e < NE) {
        int is64 = g_is64;
        int c = load_idx(ei, (size_t)NE + e, is64);
        atomicAdd(&g_deg[c], ew[e]);
    }
}

__global__ void k_dinv() {
    int i = blockIdx.x*blockDim.x + threadIdx.x;
    if (i < NN) g_dinv[i] = rsqrtf(g_deg[i]);   // deg >= 1 always
}

// ---------------- GEMM1: h1 = x @ W1 ; agg1 = dinv^2 * h1 (self loop seed) ----
__global__ void k_gemm1(const float* __restrict__ x, const float* __restrict__ W1) {
    extern __shared__ float smem[];
    float* sW = smem;              // [512][64]
    float* sX = smem + DF*DH;      // [KB][SXS] transposed

    int tid  = threadIdx.x;
    int row0 = blockIdx.x * TM;

    // load full W1 into smem
    {
        const float4* Wv = (const float4*)W1;
        float4* sWv = (float4*)sW;
        #pragma unroll
        for (int i = tid; i < DF*DH/4; i += 256) sWv[i] = Wv[i];
    }

    float acc[8][8];
    #pragma unroll
    for (int i = 0; i < 8; i++)
        #pragma unroll
        for (int j = 0; j < 8; j++) acc[i][j] = 0.0f;

    int ty = tid >> 3;   // 0..31 : 8-row group
    int tx = tid & 7;    // 0..7  : 8-col group
    const float4* xv = (const float4*)x;

    for (int kb = 0; kb < DF/KB; kb++) {
        int k0 = kb * KB;
        __syncthreads();
        // load x tile [TM][KB] transposed into sX[k][r]
        #pragma unroll
        for (int i = tid; i < TM*KB/4; i += 256) {
            int r = i >> 3;
            int q = i & 7;
            int grow = row0 + r;
            float4 v = make_float4(0.f, 0.f, 0.f, 0.f);
            if (grow < NN) v = xv[(size_t)grow*(DF/4) + (k0 >> 2) + q];
            int kk = q * 4;
            sX[(kk+0)*SXS + r] = v.x;
            sX[(kk+1)*SXS + r] = v.y;
            sX[(kk+2)*SXS + r] = v.z;
            sX[(kk+3)*SXS + r] = v.w;
        }
        __syncthreads();

        #pragma unroll 4
        for (int k = 0; k < KB; k++) {
            float4 a0 = *(const float4*)&sX[k*SXS + ty*8];
            float4 a1 = *(const float4*)&sX[k*SXS + ty*8 + 4];
            float4 b0 = *(const float4*)&sW[(k0+k)*DH + tx*8];
            float4 b1 = *(const float4*)&sW[(k0+k)*DH + tx*8 + 4];
            float a[8] = {a0.x,a0.y,a0.z,a0.w,a1.x,a1.y,a1.z,a1.w};
            float b[8] = {b0.x,b0.y,b0.z,b0.w,b1.x,b1.y,b1.z,b1.w};
            #pragma unroll
            for (int i = 0; i < 8; i++)
                #pragma unroll
                for (int j = 0; j < 8; j++)
                    acc[i][j] += a[i] * b[j];
        }
    }

    // epilogue: write h1 and agg1 = dinv^2 * h1
    #pragma unroll
    for (int i = 0; i < 8; i++) {
        int grow = row0 + ty*8 + i;
        if (grow < NN) {
            float s = g_dinv[grow]; s *= s;
            float4 v0 = make_float4(acc[i][0], acc[i][1], acc[i][2], acc[i][3]);
            float4 v1 = make_float4(acc[i][4], acc[i][5], acc[i][6], acc[i][7]);
            float4* h1v = (float4*)&g_h1[(size_t)grow*DH + tx*8];
            h1v[0] = v0; h1v[1] = v1;
            float4* agv = (float4*)&g_agg1[(size_t)grow*DH + tx*8];
            agv[0] = make_float4(s*v0.x, s*v0.y, s*v0.z, s*v0.w);
            agv[1] = make_float4(s*v1.x, s*v1.y, s*v1.z, s*v1.w);
        }
    }
}

// ---------------- edge scatter layer 1: agg1[col] += norm * h1[row] ---------
__global__ void k_edge1(const void* __restrict__ ei,
                        const float* __restrict__ ew) {
    int e = blockIdx.x*blockDim.x + threadIdx.x;
    if (e >= NE) return;
    int is64 = g_is64;
    int r = load_idx(ei, (size_t)e, is64);
    int c = load_idx(ei, (size_t)NE + e, is64);
    float w = g_dinv[r] * ew[e] * g_dinv[c];
    const float4* src = (const float4*)&g_h1[(size_t)r*DH];
    float4* dst = (float4*)&g_agg1[(size_t)c*DH];
    #pragma unroll
    for (int q = 0; q < DH/4; q++) {
        float4 v = src[q];
        atomicAdd(dst + q, make_float4(w*v.x, w*v.y, w*v.z, w*v.w));
    }
}

// ---------------- h2 = relu(agg1 + b1) @ W2 ; agg2 = dinv^2 * h2 ------------
__global__ void k_relu_gemm2(const float* __restrict__ b1,
                             const float* __restrict__ W2) {
    __shared__ float sW2[DH*NC];
    __shared__ float sb1[DH];
    int tid = threadIdx.x;
    for (int i = tid; i < DH*NC; i += blockDim.x) sW2[i] = W2[i];
    if (tid < DH) sb1[tid] = b1[tid];
    __syncthreads();

    int row = blockIdx.x*blockDim.x + tid;
    if (row >= NN) return;

    float h[DH];
    const float4* av = (const float4*)&g_agg1[(size_t)row*DH];
    #pragma unroll
    for (int q = 0; q < DH/4; q++) {
        float4 v = av[q];
        h[q*4+0] = fmaxf(v.x + sb1[q*4+0], 0.f);
        h[q*4+1] = fmaxf(v.y + sb1[q*4+1], 0.f);
        h[q*4+2] = fmaxf(v.z + sb1[q*4+2], 0.f);
        h[q*4+3] = fmaxf(v.w + sb1[q*4+3], 0.f);
    }
    float s = g_dinv[row]; s *= s;

    #pragma unroll
    for (int cc = 0; cc < NC; cc += 8) {
        float acc[8];
        #pragma unroll
        for (int j = 0; j < 8; j++) acc[j] = 0.f;
        #pragma unroll 8
        for (int k = 0; k < DH; k++) {
            float hk = h[k];
            const float4* wv = (const float4*)&sW2[k*NC + cc];
            float4 w0 = wv[0], w1 = wv[1];
            acc[0] += hk * w0.x; acc[1] += hk * w0.y;
            acc[2] += hk * w0.z; acc[3] += hk * w0.w;
            acc[4] += hk * w1.x; acc[5] += hk * w1.y;
            acc[6] += hk * w1.z; acc[7] += hk * w1.w;
        }
        float4* h2v = (float4*)&g_h2[(size_t)row*NC + cc];
        h2v[0] = make_float4(acc[0], acc[1], acc[2], acc[3]);
        h2v[1] = make_float4(acc[4], acc[5], acc[6], acc[7]);
        float4* agv = (float4*)&g_agg2[(size_t)row*NC + cc];
        agv[0] = make_float4(s*acc[0], s*acc[1], s*acc[2], s*acc[3]);
        agv[1] = make_float4(s*acc[4], s*acc[5], s*acc[6], s*acc[7]);
    }
}

// ---------------- edge scatter layer 2: agg2[col] += norm * h2[row] ---------
__global__ void k_edge2(const void* __restrict__ ei,
                        const float* __restrict__ ew) {
    int e = blockIdx.x*blockDim.x + threadIdx.x;
    if (e >= NE) return;
    int is64 = g_is64;
    int r = load_idx(ei, (size_t)e, is64);
    int c = load_idx(ei, (size_t)NE + e, is64);
    float w = g_dinv[r] * ew[e] * g_dinv[c];
    const float4* src = (const float4*)&g_h2[(size_t)r*NC];
    float4* dst = (float4*)&g_agg2[(size_t)c*NC];
    #pragma unroll
    for (int q = 0; q < NC/4; q++) {
        float4 v = src[q];
        atomicAdd(dst + q, make_float4(w*v.x, w*v.y, w*v.z, w*v.w));
    }
}

// ---------------- log_softmax(agg2 + b2) ------------------------------------
__global__ void k_logsoftmax(const float* __restrict__ b2,
                             float* __restrict__ out) {
    __shared__ float sb2[NC];
    int tid = threadIdx.x;
    if (tid < NC) sb2[tid] = b2[tid];
    __syncthreads();

    int row = blockIdx.x*blockDim.x + tid;
    if (row >= NN) return;

    float v[NC];
    const float4* av = (const float4*)&g_agg2[(size_t)row*NC];
    #pragma unroll
    for (int q = 0; q < NC/4; q++) {
        float4 t = av[q];
        v[q*4+0] = t.x + sb2[q*4+0];
        v[q*4+1] = t.y + sb2[q*4+1];
        v[q*4+2] = t.z + sb2[q*4+2];
        v[q*4+3] = t.w + sb2[q*4+3];
    }
    float m = v[0];
    #pragma unroll
    for (int c = 1; c < NC; c++) m = fmaxf(m, v[c]);
    float ssum = 0.f;
    #pragma unroll
    for (int c = 0; c < NC; c++) ssum += expf(v[c] - m);
    float lse = m + logf(ssum);

    float4* ov = (float4*)&out[(size_t)row*NC];
    #pragma unroll
    for (int q = 0; q < NC/4; q++) {
        ov[q] = make_float4(v[q*4+0]-lse, v[q*4+1]-lse, v[q*4+2]-lse, v[q*4+3]-lse);
    }
}

extern "C" void kernel_launch(void* const* d_in, const int* in_sizes, int n_in,
                              void* d_out, int out_size) {
    const float* x  = (const float*)d_in[0];
    const void*  ei = d_in[1];
    const float* ew = (const float*)d_in[2];
    const float* W1 = (const float*)d_in[3];
    const float* b1 = (const float*)d_in[4];
    const float* W2 = (const float*)d_in[5];
    const float* b2 = (const float*)d_in[6];
    float* out = (float*)d_out;

    int smem1 = (DF*DH + KB*SXS) * (int)sizeof(float);
    cudaFuncSetAttribute(k_gemm1, cudaFuncAttributeMaxDynamicSharedMemorySize, smem1);

    k_detect    <<<1, 256>>>((const int*)ei);
    k_init_deg  <<<(NN+255)/256, 256>>>();
    k_accum_deg <<<(NE+255)/256, 256>>>(ei, ew);
    k_dinv      <<<(NN+255)/256, 256>>>();
    k_gemm1     <<<(NN+TM-1)/TM, 256, smem1>>>(x, W1);
    k_edge1     <<<(NE+255)/256, 256>>>(ei, ew);
    k_relu_gemm2<<<(NN+255)/256, 256>>>(b1, W2);
    k_edge2     <<<(NE+255)/256, 256>>>(ei, ew);
    k_logsoftmax<<<(NN+255)/256, 256>>>(b2, out);
}

// round 3
// speedup vs baseline: 1.4074x; 1.4074x over previous
#include <cuda_runtime.h>
#include <math.h>

#define NN 100000
#define NE 3200000
#define DF 512
#define DH 64
#define NC 40

#define TM 256      // gemm1 row tile
#define KB 32       // gemm1 k chunk
#define SXS (TM+4)  // transposed x tile stride

#define FULL 0xffffffffu

// scratch (device globals: no allocation allowed)
__device__ int   g_is64;
__device__ float g_deg[NN];
__device__ float g_dinv[NN];
__device__ int   g_cnt[NN];
__device__ int   g_rowptr[NN+1];
__device__ int   g_cursor[NN];
__device__ int2  g_edge[NE];          // (src, bitcast(norm_w)) sorted by dst
__device__ float g_h1[(size_t)NN*DH];
__device__ float g_agg1[(size_t)NN*DH];
__device__ float g_h2[(size_t)NN*NC];

// ---------------- edge_index dtype detection --------------------------------
__global__ void k_detect(const int* __restrict__ ei32) {
    __shared__ int nz;
    if (threadIdx.x == 0) nz = 0;
    __syncthreads();
    int local = 0;
    for (int i = threadIdx.x; i < 1024; i += blockDim.x)
        if (ei32[2*i + 1] != 0) local = 1;
    if (local) atomicOr(&nz, 1);
    __syncthreads();
    if (threadIdx.x == 0) g_is64 = (nz == 0) ? 1 : 0;
}

__device__ __forceinline__ int load_idx(const void* ei, size_t pos, int is64) {
    if (is64) return (int)((const long long*)ei)[pos];
    return ((const int*)ei)[pos];
}

// ---------------- init: deg=1 (self loop), cnt=0 ----------------------------
__global__ void k_init() {
    int i = blockIdx.x*blockDim.x + threadIdx.x;
    if (i < NN) { g_deg[i] = 1.0f; g_cnt[i] = 0; }
}

// ---------------- fused weighted-degree + histogram -------------------------
__global__ void k_deg_hist(const void* __restrict__ ei,
                           const float* __restrict__ ew) {
    int e = blockIdx.x*blockDim.x + threadIdx.x;
    if (e >= NE) return;
    int is64 = g_is64;
    int c = load_idx(ei, (size_t)NE + e, is64);
    atomicAdd(&g_deg[c], ew[e]);
    atomicAdd(&g_cnt[c], 1);
}

__global__ void k_dinv() {
    int i = blockIdx.x*blockDim.x + threadIdx.x;
    if (i < NN) g_dinv[i] = rsqrtf(g_deg[i]);
}

// ---------------- single-block scan of g_cnt -> g_rowptr / g_cursor ---------
#define SCAN_T 1024
#define CHUNK  98   // 1024*98 >= 100000
__global__ void k_scan() {
    __shared__ int part[SCAN_T];
    int t = threadIdx.x;
    int lo = t * CHUNK;
    int hi = min(lo + CHUNK, NN);
    int sum = 0;
    for (int i = lo; i < hi; i++) sum += g_cnt[i];
    part[t] = sum;
    __syncthreads();
    #pragma unroll
    for (int off = 1; off < SCAN_T; off <<= 1) {
        int v = (t >= off) ? part[t-off] : 0;
        __syncthreads();
        part[t] += v;
        __syncthreads();
    }
    int run = (t > 0) ? part[t-1] : 0;
    for (int i = lo; i < hi; i++) {
        g_rowptr[i] = run;
        g_cursor[i] = run;
        run += g_cnt[i];
    }
    if (t == SCAN_T-1) g_rowptr[NN] = part[SCAN_T-1];
}

// ---------------- scatter edges into CSR ------------------------------------
__global__ void k_scatter(const void* __restrict__ ei,
                          const float* __restrict__ ew) {
    int e = blockIdx.x*blockDim.x + threadIdx.x;
    if (e >= NE) return;
    int is64 = g_is64;
    int r = load_idx(ei, (size_t)e, is64);
    int c = load_idx(ei, (size_t)NE + e, is64);
    float w = g_dinv[r] * ew[e] * g_dinv[c];
    int pos = atomicAdd(&g_cursor[c], 1);
    g_edge[pos] = make_int2(r, __float_as_int(w));
}

// ---------------- GEMM1: h1 = x @ W1 ----------------------------------------
__global__ void k_gemm1(const float* __restrict__ x, const float* __restrict__ W1) {
    extern __shared__ float smem[];
    float* sW = smem;              // [512][64]
    float* sX = smem + DF*DH;      // [KB][SXS] transposed

    int tid  = threadIdx.x;
    int row0 = blockIdx.x * TM;

    {
        const float4* Wv = (const float4*)W1;
        float4* sWv = (float4*)sW;
        #pragma unroll
        for (int i = tid; i < DF*DH/4; i += 256) sWv[i] = Wv[i];
    }

    float acc[8][8];
    #pragma unroll
    for (int i = 0; i < 8; i++)
        #pragma unroll
        for (int j = 0; j < 8; j++) acc[i][j] = 0.0f;

    int ty = tid >> 3;
    int tx = tid & 7;
    const float4* xv = (const float4*)x;

    for (int kb = 0; kb < DF/KB; kb++) {
        int k0 = kb * KB;
        __syncthreads();
        #pragma unroll
        for (int i = tid; i < TM*KB/4; i += 256) {
            int r = i >> 3;
            int q = i & 7;
            int grow = row0 + r;
            float4 v = make_float4(0.f, 0.f, 0.f, 0.f);
            if (grow < NN) v = xv[(size_t)grow*(DF/4) + (k0 >> 2) + q];
            int kk = q * 4;
            sX[(kk+0)*SXS + r] = v.x;
            sX[(kk+1)*SXS + r] = v.y;
            sX[(kk+2)*SXS + r] = v.z;
            sX[(kk+3)*SXS + r] = v.w;
        }
        __syncthreads();

        #pragma unroll 4
        for (int k = 0; k < KB; k++) {
            float4 a0 = *(const float4*)&sX[k*SXS + ty*8];
            float4 a1 = *(const float4*)&sX[k*SXS + ty*8 + 4];
            float4 b0 = *(const float4*)&sW[(k0+k)*DH + tx*8];
            float4 b1 = *(const float4*)&sW[(k0+k)*DH + tx*8 + 4];
            float a[8] = {a0.x,a0.y,a0.z,a0.w,a1.x,a1.y,a1.z,a1.w};
            float b[8] = {b0.x,b0.y,b0.z,b0.w,b1.x,b1.y,b1.z,b1.w};
            #pragma unroll
            for (int i = 0; i < 8; i++)
                #pragma unroll
                for (int j = 0; j < 8; j++)
                    acc[i][j] += a[i] * b[j];
        }
    }

    #pragma unroll
    for (int i = 0; i < 8; i++) {
        int grow = row0 + ty*8 + i;
        if (grow < NN) {
            float4* h1v = (float4*)&g_h1[(size_t)grow*DH + tx*8];
            h1v[0] = make_float4(acc[i][0], acc[i][1], acc[i][2], acc[i][3]);
            h1v[1] = make_float4(acc[i][4], acc[i][5], acc[i][6], acc[i][7]);
        }
    }
}

// ---------------- CSR aggregation layer 1: agg1[n] = sum_e w*h1[src] --------
// one warp per node; lane handles feature dims {2*lane, 2*lane+1}
__global__ void k_agg1() {
    int warp = (blockIdx.x*blockDim.x + threadIdx.x) >> 5;
    if (warp >= NN) return;
    int lane = threadIdx.x & 31;

    int start = g_rowptr[warp];
    int end   = g_rowptr[warp+1];
    float s = g_dinv[warp]; s *= s;

    float2 self = *(const float2*)&g_h1[(size_t)warp*DH + lane*2];
    float2 acc  = make_float2(s*self.x, s*self.y);

    for (int base = start; base < end; base += 32) {
        int n = min(32, end - base);
        int2 eb = (base + lane < end) ? g_edge[base + lane] : make_int2(0, 0);
        #pragma unroll 4
        for (int j = 0; j < n; j++) {
            int   s2 = __shfl_sync(FULL, eb.x, j);
            float wj = __int_as_float(__shfl_sync(FULL, eb.y, j));
            float2 hv = *(const float2*)&g_h1[(size_t)s2*DH + lane*2];
            acc.x += wj * hv.x;
            acc.y += wj * hv.y;
        }
    }
    *(float2*)&g_agg1[(size_t)warp*DH + lane*2] = acc;
}

// ---------------- h2 = relu(agg1 + b1) @ W2 ---------------------------------
__global__ void k_relu_gemm2(const float* __restrict__ b1,
                             const float* __restrict__ W2) {
    __shared__ float sW2[DH*NC];
    __shared__ float sb1[DH];
    int tid = threadIdx.x;
    for (int i = tid; i < DH*NC; i += blockDim.x) sW2[i] = W2[i];
    if (tid < DH) sb1[tid] = b1[tid];
    __syncthreads();

    int row = blockIdx.x*blockDim.x + tid;
    if (row >= NN) return;

    float h[DH];
    const float4* av = (const float4*)&g_agg1[(size_t)row*DH];
    #pragma unroll
    for (int q = 0; q < DH/4; q++) {
        float4 v = av[q];
        h[q*4+0] = fmaxf(v.x + sb1[q*4+0], 0.f);
        h[q*4+1] = fmaxf(v.y + sb1[q*4+1], 0.f);
        h[q*4+2] = fmaxf(v.z + sb1[q*4+2], 0.f);
        h[q*4+3] = fmaxf(v.w + sb1[q*4+3], 0.f);
    }

    #pragma unroll
    for (int cc = 0; cc < NC; cc += 8) {
        float acc[8];
        #pragma unroll
        for (int j = 0; j < 8; j++) acc[j] = 0.f;
        #pragma unroll 8
        for (int k = 0; k < DH; k++) {
            float hk = h[k];
            const float4* wv = (const float4*)&sW2[k*NC + cc];
            float4 w0 = wv[0], w1 = wv[1];
            acc[0] += hk * w0.x; acc[1] += hk * w0.y;
            acc[2] += hk * w0.z; acc[3] += hk * w0.w;
            acc[4] += hk * w1.x; acc[5] += hk * w1.y;
            acc[6] += hk * w1.z; acc[7] += hk * w1.w;
        }
        float4* h2v = (float4*)&g_h2[(size_t)row*NC + cc];
        h2v[0] = make_float4(acc[0], acc[1], acc[2], acc[3]);
        h2v[1] = make_float4(acc[4], acc[5], acc[6], acc[7]);
    }
}

// ---------------- CSR aggregation layer 2 + bias + log_softmax --------------
// one warp per node; lane handles class dims {lane} and {32+lane | lane<8}
__global__ void k_agg2_softmax(const float* __restrict__ b2,
                               float* __restrict__ out) {
    int warp = (blockIdx.x*blockDim.x + threadIdx.x) >> 5;
    if (warp >= NN) return;
    int lane = threadIdx.x & 31;
    bool has1 = lane < (NC - 32);

    int start = g_rowptr[warp];
    int end   = g_rowptr[warp+1];
    float s = g_dinv[warp]; s *= s;

    const float* h2row = &g_h2[(size_t)warp*NC];
    float a0 = s * h2row[lane];
    float a1 = has1 ? s * h2row[32 + lane] : 0.f;

    for (int base = start; base < end; base += 32) {
        int n = min(32, end - base);
        int2 eb = (base + lane < end) ? g_edge[base + lane] : make_int2(0, 0);
        #pragma unroll 4
        for (int j = 0; j < n; j++) {
            int   s2 = __shfl_sync(FULL, eb.x, j);
            float wj = __int_as_float(__shfl_sync(FULL, eb.y, j));
            const float* src = &g_h2[(size_t)s2*NC];
            a0 += wj * src[lane];
            if (has1) a1 += wj * src[32 + lane];
        }
    }

    a0 += b2[lane];
    if (has1) a1 += b2[32 + lane];

    // warp-wide max over the 40 logits
    float m = has1 ? fmaxf(a0, a1) : a0;
    #pragma unroll
    for (int off = 16; off > 0; off >>= 1)
        m = fmaxf(m, __shfl_xor_sync(FULL, m, off));

    float es = expf(a0 - m) + (has1 ? expf(a1 - m) : 0.f);
    #pragma unroll
    for (int off = 16; off > 0; off >>= 1)
        es += __shfl_xor_sync(FULL, es, off);

    float lse = m + logf(es);

    float* orow = &out[(size_t)warp*NC];
    orow[lane] = a0 - lse;
    if (has1) orow[32 + lane] = a1 - lse;
}

extern "C" void kernel_launch(void* const* d_in, const int* in_sizes, int n_in,
                              void* d_out, int out_size) {
    const float* x  = (const float*)d_in[0];
    const void*  ei = d_in[1];
    const float* ew = (const float*)d_in[2];
    const float* W1 = (const float*)d_in[3];
    const float* b1 = (const float*)d_in[4];
    const float* W2 = (const float*)d_in[5];
    const float* b2 = (const float*)d_in[6];
    float* out = (float*)d_out;

    int smem1 = (DF*DH + KB*SXS) * (int)sizeof(float);
    cudaFuncSetAttribute(k_gemm1, cudaFuncAttributeMaxDynamicSharedMemorySize, smem1);

    int warpGrid = (NN*32 + 255) / 256;

    k_detect       <<<1, 256>>>((const int*)ei);
    k_init         <<<(NN+255)/256, 256>>>();
    k_deg_hist     <<<(NE+255)/256, 256>>>(ei, ew);
    k_dinv         <<<(NN+255)/256, 256>>>();
    k_scan         <<<1, SCAN_T>>>();
    k_scatter      <<<(NE+255)/256, 256>>>(ei, ew);
    k_gemm1        <<<(NN+TM-1)/TM, 256, smem1>>>(x, W1);
    k_agg1         <<<warpGrid, 256>>>();
    k_relu_gemm2   <<<(NN+255)/256, 256>>>(b1, W2);
    k_agg2_softmax <<<warpGrid, 256>>>(b2, out);
}

// round 6
// speedup vs baseline: 1.7992x; 1.2784x over previous
#include <cuda_runtime.h>
#include <math.h>

#define NN 100000
#define NE 3200000
#define DF 512
#define DH 64
#define NC 40

#define FULL 0xffffffffu

// ---------------- scratch (device globals) ----------------------------------
__device__ int   g_is64;
__device__ float g_deg[NN];
__device__ float g_dinv[NN];
__device__ int   g_cnt[NN];
__device__ int   g_rowptr[NN+1];
__device__ int   g_cursor[NN];
__device__ int2  g_edge[NE];
__device__ float g_h1[(size_t)NN*DH];
__device__ float g_agg1[(size_t)NN*DH];
__device__ float g_h2[(size_t)NN*NC];
__device__ float g_BT[DH*DF];          // W1^T fp32  [n][k]

// ---------------- helpers -----------------------------------------------------
__device__ __forceinline__ void split_tf32(float v, unsigned &hi, unsigned &lo) {
    asm("cvt.rna.tf32.f32 %0, %1;" : "=r"(hi) : "f"(v));
    float r = v - __uint_as_float(hi);
    asm("cvt.rna.tf32.f32 %0, %1;" : "=r"(lo) : "f"(r));
}

__device__ __forceinline__ void mma_tf32(float* d, const unsigned* a, const unsigned* b) {
    asm volatile("mma.sync.aligned.m16n8k8.row.col.f32.tf32.tf32.f32 "
        "{%0,%1,%2,%3}, {%4,%5,%6,%7}, {%8,%9}, {%0,%1,%2,%3};"
        : "+f"(d[0]), "+f"(d[1]), "+f"(d[2]), "+f"(d[3])
        : "r"(a[0]), "r"(a[1]), "r"(a[2]), "r"(a[3]), "r"(b[0]), "r"(b[1]));
}

// ---------------- edge_index dtype detection --------------------------------
__global__ void k_detect(const int* __restrict__ ei32) {
    __shared__ int nz;
    if (threadIdx.x == 0) nz = 0;
    __syncthreads();
    int local = 0;
    for (int i = threadIdx.x; i < 1024; i += blockDim.x)
        if (ei32[2*i + 1] != 0) local = 1;
    if (local) atomicOr(&nz, 1);
    __syncthreads();
    if (threadIdx.x == 0) g_is64 = (nz == 0) ? 1 : 0;
}

__device__ __forceinline__ int load_idx(const void* ei, size_t pos, int is64) {
    if (is64) return (int)((const long long*)ei)[pos];
    return ((const int*)ei)[pos];
}

// ---------------- init --------------------------------------------------------
__global__ void k_init() {
    int i = blockIdx.x*blockDim.x + threadIdx.x;
    if (i < NN) { g_deg[i] = 1.0f; g_cnt[i] = 0; }
}

__global__ void k_deg_hist(const void* __restrict__ ei,
                           const float* __restrict__ ew) {
    int e = blockIdx.x*blockDim.x + threadIdx.x;
    if (e >= NE) return;
    int is64 = g_is64;
    int c = load_idx(ei, (size_t)NE + e, is64);
    atomicAdd(&g_deg[c], ew[e]);
    atomicAdd(&g_cnt[c], 1);
}

__global__ void k_dinv() {
    int i = blockIdx.x*blockDim.x + threadIdx.x;
    if (i < NN) g_dinv[i] = rsqrtf(g_deg[i]);
}

// ---------------- W1 transpose (fp32) ---------------------------------------
__global__ void k_transW(const float* __restrict__ W1) {
    int idx = blockIdx.x*blockDim.x + threadIdx.x;
    if (idx >= DF*DH) return;
    int k = idx / DH, n = idx % DH;
    g_BT[n*DF + k] = W1[idx];
}

// ---------------- scan + scatter (CSR build) --------------------------------
#define SCAN_T 1024
#define CHUNK  98
__global__ void k_scan() {
    __shared__ int part[SCAN_T];
    int t = threadIdx.x;
    int lo = t * CHUNK;
    int hi = min(lo + CHUNK, NN);
    int sum = 0;
    for (int i = lo; i < hi; i++) sum += g_cnt[i];
    part[t] = sum;
    __syncthreads();
    #pragma unroll
    for (int off = 1; off < SCAN_T; off <<= 1) {
        int v = (t >= off) ? part[t-off] : 0;
        __syncthreads();
        part[t] += v;
        __syncthreads();
    }
    int run = (t > 0) ? part[t-1] : 0;
    for (int i = lo; i < hi; i++) {
        g_rowptr[i] = run;
        g_cursor[i] = run;
        run += g_cnt[i];
    }
    if (t == SCAN_T-1) g_rowptr[NN] = part[SCAN_T-1];
}

__global__ void k_scatter(const void* __restrict__ ei,
                          const float* __restrict__ ew) {
    int e = blockIdx.x*blockDim.x + threadIdx.x;
    if (e >= NE) return;
    int is64 = g_is64;
    int r = load_idx(ei, (size_t)e, is64);
    int c = load_idx(ei, (size_t)NE + e, is64);
    float w = g_dinv[r] * ew[e] * g_dinv[c];
    int pos = atomicAdd(&g_cursor[c], 1);
    g_edge[pos] = make_int2(r, __float_as_int(w));
}

// ---------------- GEMM1 via 3xTF32 mma.sync ---------------------------------
// CTA: 256 thr (8 warps: warpM 0-3, warpN 0-1), tile M=128 N=64.
// K in 8 chunks of 64 through smem (fp32, stride 68 -> conflict-free frags).
#define ASTR 68
#define SM_TOT ((128+64)*ASTR*4)

__global__ void __launch_bounds__(256) k_gemm1_tf32(const float* __restrict__ x) {
    extern __shared__ float smem[];
    float* sA = smem;                 // [128][68]
    float* sB = smem + 128*ASTR;      // [64][68]
    int tid = threadIdx.x;
    int wid = tid >> 5, lane = tid & 31;
    int warpM = wid >> 1, warpN = wid & 1;
    int g = lane >> 2, tig = lane & 3;
    int row0 = blockIdx.x * 128;

    float acc[2][4][4];
    #pragma unroll
    for (int mt = 0; mt < 2; mt++)
        #pragma unroll
        for (int nt = 0; nt < 4; nt++)
            #pragma unroll
            for (int q = 0; q < 4; q++) acc[mt][nt][q] = 0.f;

    for (int ch = 0; ch < 8; ch++) {
        __syncthreads();
        // stage A chunk: x[row0..+128][ch*64..+64]
        #pragma unroll
        for (int i = 0; i < 8; i++) {
            int idx = tid + i*256;
            int r = idx >> 4, q = idx & 15;
            int grow = row0 + r;
            float4 v = make_float4(0.f,0.f,0.f,0.f);
            if (grow < NN) v = ((const float4*)x)[(size_t)grow*(DF/4) + ch*16 + q];
            *(float4*)&sA[r*ASTR + q*4] = v;
        }
        // stage B chunk: W1^T [64][ch*64..+64]
        #pragma unroll
        for (int i = 0; i < 4; i++) {
            int idx = tid + i*256;
            int r = idx >> 4, q = idx & 15;
            float4 v = ((const float4*)g_BT)[r*(DF/4) + ch*16 + q];
            *(float4*)&sB[r*ASTR + q*4] = v;
        }
        __syncthreads();

        #pragma unroll
        for (int ks = 0; ks < 8; ks++) {
            int k0 = ks*8;
            unsigned aH[2][4], aL[2][4], bH[4][2], bL[4][2];
            #pragma unroll
            for (int mt = 0; mt < 2; mt++) {
                int rb = warpM*32 + mt*16;
                split_tf32(sA[(rb+g  )*ASTR + k0+tig  ], aH[mt][0], aL[mt][0]);
                split_tf32(sA[(rb+g+8)*ASTR + k0+tig  ], aH[mt][1], aL[mt][1]);
                split_tf32(sA[(rb+g  )*ASTR + k0+tig+4], aH[mt][2], aL[mt][2]);
                split_tf32(sA[(rb+g+8)*ASTR + k0+tig+4], aH[mt][3], aL[mt][3]);
            }
            #pragma unroll
            for (int nt = 0; nt < 4; nt++) {
                int n = warpN*32 + nt*8 + g;
                split_tf32(sB[n*ASTR + k0+tig  ], bH[nt][0], bL[nt][0]);
                split_tf32(sB[n*ASTR + k0+tig+4], bH[nt][1], bL[nt][1]);
            }
            #pragma unroll
            for (int mt = 0; mt < 2; mt++)
                #pragma unroll
                for (int nt = 0; nt < 4; nt++) {
                    mma_tf32(acc[mt][nt], aH[mt], bH[nt]);
                    mma_tf32(acc[mt][nt], aH[mt], bL[nt]);
                    mma_tf32(acc[mt][nt], aL[mt], bH[nt]);
                }
        }
    }

    // epilogue: D frag (g, 2*tig) / (g+8, 2*tig) -> g_h1
    #pragma unroll
    for (int mt = 0; mt < 2; mt++) {
        #pragma unroll
        for (int half = 0; half < 2; half++) {
            int grow = row0 + warpM*32 + mt*16 + g + half*8;
            if (grow < NN) {
                float* dst = &g_h1[(size_t)grow*DH + warpN*32 + tig*2];
                #pragma unroll
                for (int nt = 0; nt < 4; nt++)
                    *(float2*)(dst + nt*8) =
                        make_float2(acc[mt][nt][half*2], acc[mt][nt][half*2+1]);
            }
        }
    }
}

// ---------------- CSR aggregation layer 1 -----------------------------------
__global__ void k_agg1() {
    int warp = (blockIdx.x*blockDim.x + threadIdx.x) >> 5;
    if (warp >= NN) return;
    int lane = threadIdx.x & 31;

    int start = g_rowptr[warp];
    int end   = g_rowptr[warp+1];
    float s = g_dinv[warp]; s *= s;

    float2 self = *(const float2*)&g_h1[(size_t)warp*DH + lane*2];
    float2 acc  = make_float2(s*self.x, s*self.y);

    for (int base = start; base < end; base += 32) {
        int n = min(32, end - base);
        int2 eb = (base + lane < end) ? g_edge[base + lane] : make_int2(0, 0);
        #pragma unroll 4
        for (int j = 0; j < n; j++) {
            int   s2 = __shfl_sync(FULL, eb.x, j);
            float wj = __int_as_float(__shfl_sync(FULL, eb.y, j));
            float2 hv = *(const float2*)&g_h1[(size_t)s2*DH + lane*2];
            acc.x += wj * hv.x;
            acc.y += wj * hv.y;
        }
    }
    *(float2*)&g_agg1[(size_t)warp*DH + lane*2] = acc;
}

// ---------------- h2 = relu(agg1 + b1) @ W2 ---------------------------------
__global__ void k_relu_gemm2(const float* __restrict__ b1,
                             const float* __restrict__ W2) {
    __shared__ float sW2[DH*NC];
    __shared__ float sb1[DH];
    int tid = threadIdx.x;
    for (int i = tid; i < DH*NC; i += blockDim.x) sW2[i] = W2[i];
    if (tid < DH) sb1[tid] = b1[tid];
    __syncthreads();

    int row = blockIdx.x*blockDim.x + tid;
    if (row >= NN) return;

    float h[DH];
    const float4* av = (const float4*)&g_agg1[(size_t)row*DH];
    #pragma unroll
    for (int q = 0; q < DH/4; q++) {
        float4 v = av[q];
        h[q*4+0] = fmaxf(v.x + sb1[q*4+0], 0.f);
        h[q*4+1] = fmaxf(v.y + sb1[q*4+1], 0.f);
        h[q*4+2] = fmaxf(v.z + sb1[q*4+2], 0.f);
        h[q*4+3] = fmaxf(v.w + sb1[q*4+3], 0.f);
    }

    #pragma unroll
    for (int cc = 0; cc < NC; cc += 8) {
        float acc[8];
        #pragma unroll
        for (int j = 0; j < 8; j++) acc[j] = 0.f;
        #pragma unroll 8
        for (int k = 0; k < DH; k++) {
            float hk = h[k];
            const float4* wv = (const float4*)&sW2[k*NC + cc];
            float4 w0 = wv[0], w1 = wv[1];
            acc[0] += hk * w0.x; acc[1] += hk * w0.y;
            acc[2] += hk * w0.z; acc[3] += hk * w0.w;
            acc[4] += hk * w1.x; acc[5] += hk * w1.y;
            acc[6] += hk * w1.z; acc[7] += hk * w1.w;
        }
        float4* h2v = (float4*)&g_h2[(size_t)row*NC + cc];
        h2v[0] = make_float4(acc[0], acc[1], acc[2], acc[3]);
        h2v[1] = make_float4(acc[4], acc[5], acc[6], acc[7]);
    }
}

// ---------------- CSR aggregation layer 2 + bias + log_softmax --------------
__global__ void k_agg2_softmax(const float* __restrict__ b2,
                               float* __restrict__ out) {
    int warp = (blockIdx.x*blockDim.x + threadIdx.x) >> 5;
    if (warp >= NN) return;
    int lane = threadIdx.x & 31;
    bool has1 = lane < (NC - 32);

    int start = g_rowptr[warp];
    int end   = g_rowptr[warp+1];
    float s = g_dinv[warp]; s *= s;

    const float* h2row = &g_h2[(size_t)warp*NC];
    float a0 = s * h2row[lane];
    float a1 = has1 ? s * h2row[32 + lane] : 0.f;

    for (int base = start; base < end; base += 32) {
        int n = min(32, end - base);
        int2 eb = (base + lane < end) ? g_edge[base + lane] : make_int2(0, 0);
        #pragma unroll 4
        for (int j = 0; j < n; j++) {
            int   s2 = __shfl_sync(FULL, eb.x, j);
            float wj = __int_as_float(__shfl_sync(FULL, eb.y, j));
            const float* src = &g_h2[(size_t)s2*NC];
            a0 += wj * src[lane];
            if (has1) a1 += wj * src[32 + lane];
        }
    }

    a0 += b2[lane];
    if (has1) a1 += b2[32 + lane];

    float m = has1 ? fmaxf(a0, a1) : a0;
    #pragma unroll
    for (int off = 16; off > 0; off >>= 1)
        m = fmaxf(m, __shfl_xor_sync(FULL, m, off));

    float es = expf(a0 - m) + (has1 ? expf(a1 - m) : 0.f);
    #pragma unroll
    for (int off = 16; off > 0; off >>= 1)
        es += __shfl_xor_sync(FULL, es, off);

    float lse = m + logf(es);

    float* orow = &out[(size_t)warp*NC];
    orow[lane] = a0 - lse;
    if (has1) orow[32 + lane] = a1 - lse;
}

extern "C" void kernel_launch(void* const* d_in, const int* in_sizes, int n_in,
                              void* d_out, int out_size) {
    const float* x  = (const float*)d_in[0];
    const void*  ei = d_in[1];
    const float* ew = (const float*)d_in[2];
    const float* W1 = (const float*)d_in[3];
    const float* b1 = (const float*)d_in[4];
    const float* W2 = (const float*)d_in[5];
    const float* b2 = (const float*)d_in[6];
    float* out = (float*)d_out;

    cudaFuncSetAttribute(k_gemm1_tf32, cudaFuncAttributeMaxDynamicSharedMemorySize, SM_TOT);

    int warpGrid = (NN*32 + 255) / 256;

    k_detect       <<<1, 256>>>((const int*)ei);
    k_init         <<<(NN+255)/256, 256>>>();
    k_transW       <<<(DF*DH+255)/256, 256>>>(W1);
    k_deg_hist     <<<(NE+255)/256, 256>>>(ei, ew);
    k_dinv         <<<(NN+255)/256, 256>>>();
    k_scan         <<<1, SCAN_T>>>();
    k_scatter      <<<(NE+255)/256, 256>>>(ei, ew);
    k_gemm1_tf32   <<<(NN+127)/128, 256, SM_TOT>>>(x);
    k_agg1         <<<warpGrid, 256>>>();
    k_relu_gemm2   <<<(NN+255)/256, 256>>>(b1, W2);
    k_agg2_softmax <<<warpGrid, 256>>>(b2, out);
}

// round 7
// speedup vs baseline: 1.8279x; 1.0159x over previous
#include <cuda_runtime.h>
#include <cuda_fp16.h>
#include <math.h>

#define NN 100000
#define NE 3200000
#define DF 512
#define DH 64
#define NC 40

#define FULL 0xffffffffu

// ---------------- scratch (device globals) ----------------------------------
__device__ int     g_is64;
__device__ float   g_deg[NN];
__device__ float   g_dinv[NN];
__device__ int     g_cnt[NN];
__device__ int     g_rowptr[NN+1];
__device__ int     g_cursor[NN];
__device__ int2    g_edge[NE];
__device__ __half2 g_h1h[(size_t)NN*(DH/2)];   // h1 as fp16 pairs
__device__ float   g_agg1[(size_t)NN*DH];
__device__ __half2 g_h2h[(size_t)NN*(NC/2)];   // h2 as fp16 pairs
__device__ float   g_BT[DH*DF];                // W1^T fp32  [n][k]

// ---------------- helpers -----------------------------------------------------
__device__ __forceinline__ void split_tf32(float v, unsigned &hi, unsigned &lo) {
    asm("cvt.rna.tf32.f32 %0, %1;" : "=r"(hi) : "f"(v));
    float r = v - __uint_as_float(hi);
    asm("cvt.rna.tf32.f32 %0, %1;" : "=r"(lo) : "f"(r));
}

__device__ __forceinline__ void mma_tf32(float* d, const unsigned* a, const unsigned* b) {
    asm volatile("mma.sync.aligned.m16n8k8.row.col.f32.tf32.tf32.f32 "
        "{%0,%1,%2,%3}, {%4,%5,%6,%7}, {%8,%9}, {%0,%1,%2,%3};"
        : "+f"(d[0]), "+f"(d[1]), "+f"(d[2]), "+f"(d[3])
        : "r"(a[0]), "r"(a[1]), "r"(a[2]), "r"(a[3]), "r"(b[0]), "r"(b[1]));
}

__device__ __forceinline__ int load_idx(const void* ei, size_t pos, int is64) {
    if (is64) return (int)((const long long*)ei)[pos];
    return ((const int*)ei)[pos];
}

// ---------------- init (+dtype detect in block 0) ---------------------------
__global__ void k_init(const int* __restrict__ ei32) {
    int i = blockIdx.x*blockDim.x + threadIdx.x;
    if (i < NN) { g_deg[i] = 1.0f; g_cnt[i] = 0; }
    if (blockIdx.x == 0) {
        __shared__ int nz;
        if (threadIdx.x == 0) nz = 0;
        __syncthreads();
        int local = 0;
        for (int s = threadIdx.x; s < 1024; s += blockDim.x)
            if (ei32[2*s + 1] != 0) local = 1;
        if (local) atomicOr(&nz, 1);
        __syncthreads();
        if (threadIdx.x == 0) g_is64 = (nz == 0) ? 1 : 0;
    }
}

__global__ void k_deg_hist(const void* __restrict__ ei,
                           const float* __restrict__ ew) {
    int e = blockIdx.x*blockDim.x + threadIdx.x;
    if (e >= NE) return;
    int is64 = g_is64;
    int c = load_idx(ei, (size_t)NE + e, is64);
    atomicAdd(&g_deg[c], ew[e]);
    atomicAdd(&g_cnt[c], 1);
}

__global__ void k_dinv() {
    int i = blockIdx.x*blockDim.x + threadIdx.x;
    if (i < NN) g_dinv[i] = rsqrtf(g_deg[i]);
}

// ---------------- W1 transpose (fp32) ---------------------------------------
__global__ void k_transW(const float* __restrict__ W1) {
    int idx = blockIdx.x*blockDim.x + threadIdx.x;
    if (idx >= DF*DH) return;
    int k = idx / DH, n = idx % DH;
    g_BT[n*DF + k] = W1[idx];
}

// ---------------- scan + scatter (CSR build) --------------------------------
#define SCAN_T 1024
#define CHUNK  98
__global__ void k_scan() {
    __shared__ int part[SCAN_T];
    int t = threadIdx.x;
    int lo = t * CHUNK;
    int hi = min(lo + CHUNK, NN);
    int sum = 0;
    for (int i = lo; i < hi; i++) sum += g_cnt[i];
    part[t] = sum;
    __syncthreads();
    #pragma unroll
    for (int off = 1; off < SCAN_T; off <<= 1) {
        int v = (t >= off) ? part[t-off] : 0;
        __syncthreads();
        part[t] += v;
        __syncthreads();
    }
    int run = (t > 0) ? part[t-1] : 0;
    for (int i = lo; i < hi; i++) {
        g_rowptr[i] = run;
        g_cursor[i] = run;
        run += g_cnt[i];
    }
    if (t == SCAN_T-1) g_rowptr[NN] = part[SCAN_T-1];
}

__global__ void k_scatter(const void* __restrict__ ei,
                          const float* __restrict__ ew) {
    int e = blockIdx.x*blockDim.x + threadIdx.x;
    if (e >= NE) return;
    int is64 = g_is64;
    int r = load_idx(ei, (size_t)e, is64);
    int c = load_idx(ei, (size_t)NE + e, is64);
    float w = g_dinv[r] * ew[e] * g_dinv[c];
    int pos = atomicAdd(&g_cursor[c], 1);
    g_edge[pos] = make_int2(r, __float_as_int(w));
}

// ---------------- GEMM1 via 3xTF32 mma.sync, fp16 output --------------------
#define ASTR 68
#define SM_TOT ((128+64)*ASTR*4)

__global__ void __launch_bounds__(256) k_gemm1_tf32(const float* __restrict__ x) {
    extern __shared__ float smem[];
    float* sA = smem;                 // [128][68]
    float* sB = smem + 128*ASTR;      // [64][68]
    int tid = threadIdx.x;
    int wid = tid >> 5, lane = tid & 31;
    int warpM = wid >> 1, warpN = wid & 1;
    int g = lane >> 2, tig = lane & 3;
    int row0 = blockIdx.x * 128;

    float acc[2][4][4];
    #pragma unroll
    for (int mt = 0; mt < 2; mt++)
        #pragma unroll
        for (int nt = 0; nt < 4; nt++)
            #pragma unroll
            for (int q = 0; q < 4; q++) acc[mt][nt][q] = 0.f;

    for (int ch = 0; ch < 8; ch++) {
        __syncthreads();
        #pragma unroll
        for (int i = 0; i < 8; i++) {
            int idx = tid + i*256;
            int r = idx >> 4, q = idx & 15;
            int grow = row0 + r;
            float4 v = make_float4(0.f,0.f,0.f,0.f);
            if (grow < NN) v = ((const float4*)x)[(size_t)grow*(DF/4) + ch*16 + q];
            *(float4*)&sA[r*ASTR + q*4] = v;
        }
        #pragma unroll
        for (int i = 0; i < 4; i++) {
            int idx = tid + i*256;
            int r = idx >> 4, q = idx & 15;
            float4 v = ((const float4*)g_BT)[r*(DF/4) + ch*16 + q];
            *(float4*)&sB[r*ASTR + q*4] = v;
        }
        __syncthreads();

        #pragma unroll
        for (int ks = 0; ks < 8; ks++) {
            int k0 = ks*8;
            unsigned aH[2][4], aL[2][4], bH[4][2], bL[4][2];
            #pragma unroll
            for (int mt = 0; mt < 2; mt++) {
                int rb = warpM*32 + mt*16;
                split_tf32(sA[(rb+g  )*ASTR + k0+tig  ], aH[mt][0], aL[mt][0]);
                split_tf32(sA[(rb+g+8)*ASTR + k0+tig  ], aH[mt][1], aL[mt][1]);
                split_tf32(sA[(rb+g  )*ASTR + k0+tig+4], aH[mt][2], aL[mt][2]);
                split_tf32(sA[(rb+g+8)*ASTR + k0+tig+4], aH[mt][3], aL[mt][3]);
            }
            #pragma unroll
            for (int nt = 0; nt < 4; nt++) {
                int n = warpN*32 + nt*8 + g;
                split_tf32(sB[n*ASTR + k0+tig  ], bH[nt][0], bL[nt][0]);
                split_tf32(sB[n*ASTR + k0+tig+4], bH[nt][1], bL[nt][1]);
            }
            #pragma unroll
            for (int mt = 0; mt < 2; mt++)
                #pragma unroll
                for (int nt = 0; nt < 4; nt++) {
                    mma_tf32(acc[mt][nt], aH[mt], bH[nt]);
                    mma_tf32(acc[mt][nt], aH[mt], bL[nt]);
                    mma_tf32(acc[mt][nt], aL[mt], bH[nt]);
                }
        }
    }

    // epilogue: D frag (g, 2*tig) -> g_h1h (fp16 pairs; features 2tig,2tig+1)
    #pragma unroll
    for (int mt = 0; mt < 2; mt++) {
        #pragma unroll
        for (int half = 0; half < 2; half++) {
            int grow = row0 + warpM*32 + mt*16 + g + half*8;
            if (grow < NN) {
                __half2* dst = &g_h1h[(size_t)grow*(DH/2) + warpN*16 + tig];
                #pragma unroll
                for (int nt = 0; nt < 4; nt++)
                    dst[nt*4] = __floats2half2_rn(acc[mt][nt][half*2],
                                                  acc[mt][nt][half*2+1]);
            }
        }
    }
}

// ---------------- CSR aggregation layer 1 (fp16 gather, fp32 accum) ---------
__global__ void k_agg1() {
    int warp = (blockIdx.x*blockDim.x + threadIdx.x) >> 5;
    if (warp >= NN) return;
    int lane = threadIdx.x & 31;

    int start = g_rowptr[warp];
    int end   = g_rowptr[warp+1];
    float s = g_dinv[warp]; s *= s;

    float2 self = __half22float2(g_h1h[(size_t)warp*(DH/2) + lane]);
    float2 acc  = make_float2(s*self.x, s*self.y);

    int2 eb = (start + lane < end) ? g_edge[start + lane] : make_int2(0, 0);
    for (int base = start; base < end; base += 32) {
        int n = min(32, end - base);
        int2 ebn = (base + 32 + lane < end) ? g_edge[base + 32 + lane]
                                            : make_int2(0, 0);
        #pragma unroll 8
        for (int j = 0; j < n; j++) {
            int   s2 = __shfl_sync(FULL, eb.x, j);
            float wj = __int_as_float(__shfl_sync(FULL, eb.y, j));
            float2 hv = __half22float2(g_h1h[(size_t)s2*(DH/2) + lane]);
            acc.x += wj * hv.x;
            acc.y += wj * hv.y;
        }
        eb = ebn;
    }
    *(float2*)&g_agg1[(size_t)warp*DH + lane*2] = acc;
}

// ---------------- h2 = relu(agg1 + b1) @ W2  (fp16 output) ------------------
__global__ void k_relu_gemm2(const float* __restrict__ b1,
                             const float* __restrict__ W2) {
    __shared__ float sW2[DH*NC];
    __shared__ float sb1[DH];
    int tid = threadIdx.x;
    for (int i = tid; i < DH*NC; i += blockDim.x) sW2[i] = W2[i];
    if (tid < DH) sb1[tid] = b1[tid];
    __syncthreads();

    int row = blockIdx.x*blockDim.x + tid;
    if (row >= NN) return;

    float h[DH];
    const float4* av = (const float4*)&g_agg1[(size_t)row*DH];
    #pragma unroll
    for (int q = 0; q < DH/4; q++) {
        float4 v = av[q];
        h[q*4+0] = fmaxf(v.x + sb1[q*4+0], 0.f);
        h[q*4+1] = fmaxf(v.y + sb1[q*4+1], 0.f);
        h[q*4+2] = fmaxf(v.z + sb1[q*4+2], 0.f);
        h[q*4+3] = fmaxf(v.w + sb1[q*4+3], 0.f);
    }

    #pragma unroll
    for (int cc = 0; cc < NC; cc += 8) {
        float acc[8];
        #pragma unroll
        for (int j = 0; j < 8; j++) acc[j] = 0.f;
        #pragma unroll 8
        for (int k = 0; k < DH; k++) {
            float hk = h[k];
            const float4* wv = (const float4*)&sW2[k*NC + cc];
            float4 w0 = wv[0], w1 = wv[1];
            acc[0] += hk * w0.x; acc[1] += hk * w0.y;
            acc[2] += hk * w0.z; acc[3] += hk * w0.w;
            acc[4] += hk * w1.x; acc[5] += hk * w1.y;
            acc[6] += hk * w1.z; acc[7] += hk * w1.w;
        }
        __half2* dst = &g_h2h[(size_t)row*(NC/2) + cc/2];
        dst[0] = __floats2half2_rn(acc[0], acc[1]);
        dst[1] = __floats2half2_rn(acc[2], acc[3]);
        dst[2] = __floats2half2_rn(acc[4], acc[5]);
        dst[3] = __floats2half2_rn(acc[6], acc[7]);
    }
}

// ---------------- CSR aggregation layer 2 + bias + log_softmax --------------
// lanes 0..19 each own class pair {2*lane, 2*lane+1}
__global__ void k_agg2_softmax(const float* __restrict__ b2,
                               float* __restrict__ out) {
    int warp = (blockIdx.x*blockDim.x + threadIdx.x) >> 5;
    if (warp >= NN) return;
    int lane = threadIdx.x & 31;
    bool act = lane < (NC/2);

    int start = g_rowptr[warp];
    int end   = g_rowptr[warp+1];
    float s = g_dinv[warp]; s *= s;

    float a0 = 0.f, a1 = 0.f;
    if (act) {
        float2 self = __half22float2(g_h2h[(size_t)warp*(NC/2) + lane]);
        a0 = s*self.x; a1 = s*self.y;
    }

    int2 eb = (start + lane < end) ? g_edge[start + lane] : make_int2(0, 0);
    for (int base = start; base < end; base += 32) {
        int n = min(32, end - base);
        int2 ebn = (base + 32 + lane < end) ? g_edge[base + 32 + lane]
                                            : make_int2(0, 0);
        #pragma unroll 8
        for (int j = 0; j < n; j++) {
            int   s2 = __shfl_sync(FULL, eb.x, j);
            float wj = __int_as_float(__shfl_sync(FULL, eb.y, j));
            if (act) {
                float2 hv = __half22float2(g_h2h[(size_t)s2*(NC/2) + lane]);
                a0 += wj * hv.x;
                a1 += wj * hv.y;
            }
        }
        eb = ebn;
    }

    if (act) {
        a0 += b2[lane*2];
        a1 += b2[lane*2 + 1];
    }

    float m = act ? fmaxf(a0, a1) : -1e30f;
    #pragma unroll
    for (int off = 16; off > 0; off >>= 1)
        m = fmaxf(m, __shfl_xor_sync(FULL, m, off));

    float es = act ? (expf(a0 - m) + expf(a1 - m)) : 0.f;
    #pragma unroll
    for (int off = 16; off > 0; off >>= 1)
        es += __shfl_xor_sync(FULL, es, off);

    float lse = m + logf(es);

    if (act) {
        *(float2*)&out[(size_t)warp*NC + lane*2] = make_float2(a0 - lse, a1 - lse);
    }
}

extern "C" void kernel_launch(void* const* d_in, const int* in_sizes, int n_in,
                              void* d_out, int out_size) {
    const float* x  = (const float*)d_in[0];
    const void*  ei = d_in[1];
    const float* ew = (const float*)d_in[2];
    const float* W1 = (const float*)d_in[3];
    const float* b1 = (const float*)d_in[4];
    const float* W2 = (const float*)d_in[5];
    const float* b2 = (const float*)d_in[6];
    float* out = (float*)d_out;

    cudaFuncSetAttribute(k_gemm1_tf32, cudaFuncAttributeMaxDynamicSharedMemorySize, SM_TOT);

    int warpGrid = (NN*32 + 255) / 256;

    k_init         <<<(NN+255)/256, 256>>>((const int*)ei);
    k_transW       <<<(DF*DH+255)/256, 256>>>(W1);
    k_deg_hist     <<<(NE+255)/256, 256>>>(ei, ew);
    k_dinv         <<<(NN+255)/256, 256>>>();
    k_scan         <<<1, SCAN_T>>>();
    k_scatter      <<<(NE+255)/256, 256>>>(ei, ew);
    k_gemm1_tf32   <<<(NN+127)/128, 256, SM_TOT>>>(x);
    k_agg1         <<<warpGrid, 256>>>();
    k_relu_gemm2   <<<(NN+255)/256, 256>>>(b1, W2);
    k_agg2_softmax <<<warpGrid, 256>>>(b2, out);
}

// round 8
// speedup vs baseline: 1.8761x; 1.0264x over previous
#include <cuda_runtime.h>
#include <cuda_fp16.h>
#include <math.h>

#define NN 100000
#define NE 3200000
#define DF 512
#define DH 64
#define NC 40

#define FULL 0xffffffffu

// ---------------- scratch (device globals) ----------------------------------
__device__ int     g_is64;
__device__ float   g_deg[NN];
__device__ float   g_dinv[NN];
__device__ int     g_cnt[NN];
__device__ int     g_rowptr[NN+1];
__device__ int     g_cursor[NN];
__device__ int2    g_edge[NE];
__device__ __half2 g_h1h[(size_t)NN*(DH/2)];   // h1 as fp16 pairs
__device__ float   g_agg1[(size_t)NN*DH];
__device__ __half2 g_h2h[(size_t)NN*(NC/2)];   // h2 as fp16 pairs
__device__ float   g_BT[DH*DF];                // W1^T fp32  [n][k]

// ---------------- helpers -----------------------------------------------------
__device__ __forceinline__ unsigned smem_u32(const void* p) {
    unsigned a;
    asm("{ .reg .u64 t; cvta.to.shared.u64 t, %1; cvt.u32.u64 %0, t; }"
        : "=r"(a) : "l"(p));
    return a;
}

__device__ __forceinline__ void split_tf32(float v, unsigned &hi, unsigned &lo) {
    asm("cvt.rna.tf32.f32 %0, %1;" : "=r"(hi) : "f"(v));
    float r = v - __uint_as_float(hi);
    asm("cvt.rna.tf32.f32 %0, %1;" : "=r"(lo) : "f"(r));
}

__device__ __forceinline__ void mma_tf32(float* d, const unsigned* a, const unsigned* b) {
    asm volatile("mma.sync.aligned.m16n8k8.row.col.f32.tf32.tf32.f32 "
        "{%0,%1,%2,%3}, {%4,%5,%6,%7}, {%8,%9}, {%0,%1,%2,%3};"
        : "+f"(d[0]), "+f"(d[1]), "+f"(d[2]), "+f"(d[3])
        : "r"(a[0]), "r"(a[1]), "r"(a[2]), "r"(a[3]), "r"(b[0]), "r"(b[1]));
}

__device__ __forceinline__ void cp16(unsigned dst, const void* src) {
    asm volatile("cp.async.cg.shared.global [%0], [%1], 16;"
                 :: "r"(dst), "l"(src) : "memory");
}

__device__ __forceinline__ int load_idx(const void* ei, size_t pos, int is64) {
    if (is64) return (int)((const long long*)ei)[pos];
    return ((const int*)ei)[pos];
}

// ---------------- init (+dtype detect in block 0) ---------------------------
__global__ void k_init(const int* __restrict__ ei32) {
    int i = blockIdx.x*blockDim.x + threadIdx.x;
    if (i < NN) { g_deg[i] = 1.0f; g_cnt[i] = 0; }
    if (blockIdx.x == 0) {
        __shared__ int nz;
        if (threadIdx.x == 0) nz = 0;
        __syncthreads();
        int local = 0;
        for (int s = threadIdx.x; s < 1024; s += blockDim.x)
            if (ei32[2*s + 1] != 0) local = 1;
        if (local) atomicOr(&nz, 1);
        __syncthreads();
        if (threadIdx.x == 0) g_is64 = (nz == 0) ? 1 : 0;
    }
}

__global__ void k_deg_hist(const void* __restrict__ ei,
                           const float* __restrict__ ew) {
    int e = blockIdx.x*blockDim.x + threadIdx.x;
    if (e >= NE) return;
    int is64 = g_is64;
    int c = load_idx(ei, (size_t)NE + e, is64);
    atomicAdd(&g_deg[c], ew[e]);
    atomicAdd(&g_cnt[c], 1);
}

__global__ void k_dinv() {
    int i = blockIdx.x*blockDim.x + threadIdx.x;
    if (i < NN) g_dinv[i] = rsqrtf(g_deg[i]);
}

// ---------------- W1 transpose (fp32) ---------------------------------------
__global__ void k_transW(const float* __restrict__ W1) {
    int idx = blockIdx.x*blockDim.x + threadIdx.x;
    if (idx >= DF*DH) return;
    int k = idx / DH, n = idx % DH;
    g_BT[n*DF + k] = W1[idx];
}

// ---------------- scan + scatter (CSR build) --------------------------------
#define SCAN_T 1024
#define CHUNK  98
__global__ void k_scan() {
    __shared__ int part[SCAN_T];
    int t = threadIdx.x;
    int lo = t * CHUNK;
    int hi = min(lo + CHUNK, NN);
    int sum = 0;
    for (int i = lo; i < hi; i++) sum += g_cnt[i];
    part[t] = sum;
    __syncthreads();
    #pragma unroll
    for (int off = 1; off < SCAN_T; off <<= 1) {
        int v = (t >= off) ? part[t-off] : 0;
        __syncthreads();
        part[t] += v;
        __syncthreads();
    }
    int run = (t > 0) ? part[t-1] : 0;
    for (int i = lo; i < hi; i++) {
        g_rowptr[i] = run;
        g_cursor[i] = run;
        run += g_cnt[i];
    }
    if (t == SCAN_T-1) g_rowptr[NN] = part[SCAN_T-1];
}

__global__ void k_scatter(const void* __restrict__ ei,
                          const float* __restrict__ ew) {
    int e = blockIdx.x*blockDim.x + threadIdx.x;
    if (e >= NE) return;
    int is64 = g_is64;
    int r = load_idx(ei, (size_t)e, is64);
    int c = load_idx(ei, (size_t)NE + e, is64);
    float w = g_dinv[r] * ew[e] * g_dinv[c];
    int pos = atomicAdd(&g_cursor[c], 1);
    g_edge[pos] = make_int2(r, __float_as_int(w));
}

// ---------------- GEMM1: 3xTF32 mma.sync + cp.async double buffer -----------
// CTA: 256 thr (8 warps: warpM 0-3, warpN 0-1), tile M=128 N=64, K chunks of 64.
#define ASTR 68
#define AFL  (128*ASTR)          // floats per A buffer
#define BFL  (64*ASTR)           // floats per B buffer
#define SM_TOT ((2*AFL + 2*BFL)*4)

__global__ void __launch_bounds__(256) k_gemm1_tf32(const float* __restrict__ x) {
    extern __shared__ float smem[];
    unsigned sbase = smem_u32(smem);
    int tid = threadIdx.x;
    int wid = tid >> 5, lane = tid & 31;
    int warpM = wid >> 1, warpN = wid & 1;
    int g = lane >> 2, tig = lane & 3;
    int row0 = blockIdx.x * 128;

    // staging indices (per thread, fixed)
    int ar = 0, aq = 0, br = 0, bq = 0;
    {
        // A: 2048 float4s over 256 threads -> 8 each; B: 1024 -> 4 each
        ar = tid >> 4; aq = tid & 15;   // base row/col; rows advance by 16 per i
        br = tid >> 4; bq = tid & 15;
    }

    // prefetch chunk 0 into buffer 0
    {
        #pragma unroll
        for (int i = 0; i < 8; i++) {
            int r = ar + i*16;
            int grow = min(row0 + r, NN-1);
            cp16(sbase + (r*ASTR + aq*4)*4,
                 (const void*)&x[(size_t)grow*DF + aq*4]);
        }
        #pragma unroll
        for (int i = 0; i < 4; i++) {
            int r = br + i*16;
            cp16(sbase + (2*AFL + r*ASTR + bq*4)*4,
                 (const void*)&g_BT[(size_t)r*DF + bq*4]);
        }
        asm volatile("cp.async.commit_group;" ::: "memory");
    }

    float acc[2][4][4];
    #pragma unroll
    for (int mt = 0; mt < 2; mt++)
        #pragma unroll
        for (int nt = 0; nt < 4; nt++)
            #pragma unroll
            for (int q = 0; q < 4; q++) acc[mt][nt][q] = 0.f;

    for (int ch = 0; ch < 8; ch++) {
        int cur = ch & 1;
        if (ch < 7) {
            int nxt = (ch+1) & 1;
            int koff = (ch+1)*64;
            #pragma unroll
            for (int i = 0; i < 8; i++) {
                int r = ar + i*16;
                int grow = min(row0 + r, NN-1);
                cp16(sbase + (nxt*AFL + r*ASTR + aq*4)*4,
                     (const void*)&x[(size_t)grow*DF + koff + aq*4]);
            }
            #pragma unroll
            for (int i = 0; i < 4; i++) {
                int r = br + i*16;
                cp16(sbase + (2*AFL + nxt*BFL + r*ASTR + bq*4)*4,
                     (const void*)&g_BT[(size_t)r*DF + koff + bq*4]);
            }
            asm volatile("cp.async.commit_group;" ::: "memory");
            asm volatile("cp.async.wait_group 1;" ::: "memory");
        } else {
            asm volatile("cp.async.wait_group 0;" ::: "memory");
        }
        __syncthreads();

        const float* sA = smem + cur*AFL;
        const float* sB = smem + 2*AFL + cur*BFL;

        #pragma unroll
        for (int ks = 0; ks < 8; ks++) {
            int k0 = ks*8;
            unsigned aH[2][4], aL[2][4], bH[4][2], bL[4][2];
            #pragma unroll
            for (int mt = 0; mt < 2; mt++) {
                int rb = warpM*32 + mt*16;
                split_tf32(sA[(rb+g  )*ASTR + k0+tig  ], aH[mt][0], aL[mt][0]);
                split_tf32(sA[(rb+g+8)*ASTR + k0+tig  ], aH[mt][1], aL[mt][1]);
                split_tf32(sA[(rb+g  )*ASTR + k0+tig+4], aH[mt][2], aL[mt][2]);
                split_tf32(sA[(rb+g+8)*ASTR + k0+tig+4], aH[mt][3], aL[mt][3]);
            }
            #pragma unroll
            for (int nt = 0; nt < 4; nt++) {
                int n = warpN*32 + nt*8 + g;
                split_tf32(sB[n*ASTR + k0+tig  ], bH[nt][0], bL[nt][0]);
                split_tf32(sB[n*ASTR + k0+tig+4], bH[nt][1], bL[nt][1]);
            }
            #pragma unroll
            for (int mt = 0; mt < 2; mt++)
                #pragma unroll
                for (int nt = 0; nt < 4; nt++) {
                    mma_tf32(acc[mt][nt], aH[mt], bH[nt]);
                    mma_tf32(acc[mt][nt], aH[mt], bL[nt]);
                    mma_tf32(acc[mt][nt], aL[mt], bH[nt]);
                }
        }
        __syncthreads();
    }

    // epilogue: D frag (g, 2*tig) -> g_h1h (fp16 pairs)
    #pragma unroll
    for (int mt = 0; mt < 2; mt++) {
        #pragma unroll
        for (int half = 0; half < 2; half++) {
            int grow = row0 + warpM*32 + mt*16 + g + half*8;
            if (grow < NN) {
                __half2* dst = &g_h1h[(size_t)grow*(DH/2) + warpN*16 + tig];
                #pragma unroll
                for (int nt = 0; nt < 4; nt++)
                    dst[nt*4] = __floats2half2_rn(acc[mt][nt][half*2],
                                                  acc[mt][nt][half*2+1]);
            }
        }
    }
}

// ---------------- CSR aggregation layer 1 (fp16 gather, fp32 accum) ---------
__global__ void k_agg1() {
    int warp = (blockIdx.x*blockDim.x + threadIdx.x) >> 5;
    if (warp >= NN) return;
    int lane = threadIdx.x & 31;

    int start = g_rowptr[warp];
    int end   = g_rowptr[warp+1];
    float s = g_dinv[warp]; s *= s;

    float2 self = __half22float2(g_h1h[(size_t)warp*(DH/2) + lane]);
    float2 acc  = make_float2(s*self.x, s*self.y);

    int2 eb = (start + lane < end) ? g_edge[start + lane] : make_int2(0, 0);
    for (int base = start; base < end; base += 32) {
        int n = min(32, end - base);
        int2 ebn = (base + 32 + lane < end) ? g_edge[base + 32 + lane]
                                            : make_int2(0, 0);
        #pragma unroll 8
        for (int j = 0; j < n; j++) {
            int   s2 = __shfl_sync(FULL, eb.x, j);
            float wj = __int_as_float(__shfl_sync(FULL, eb.y, j));
            float2 hv = __half22float2(g_h1h[(size_t)s2*(DH/2) + lane]);
            acc.x += wj * hv.x;
            acc.y += wj * hv.y;
        }
        eb = ebn;
    }
    *(float2*)&g_agg1[(size_t)warp*DH + lane*2] = acc;
}

// ---------------- h2 = relu(agg1 + b1) @ W2  (fp16 output) ------------------
__global__ void k_relu_gemm2(const float* __restrict__ b1,
                             const float* __restrict__ W2) {
    __shared__ float sW2[DH*NC];
    __shared__ float sb1[DH];
    int tid = threadIdx.x;
    for (int i = tid; i < DH*NC; i += blockDim.x) sW2[i] = W2[i];
    if (tid < DH) sb1[tid] = b1[tid];
    __syncthreads();

    int row = blockIdx.x*blockDim.x + tid;
    if (row >= NN) return;

    float h[DH];
    const float4* av = (const float4*)&g_agg1[(size_t)row*DH];
    #pragma unroll
    for (int q = 0; q < DH/4; q++) {
        float4 v = av[q];
        h[q*4+0] = fmaxf(v.x + sb1[q*4+0], 0.f);
        h[q*4+1] = fmaxf(v.y + sb1[q*4+1], 0.f);
        h[q*4+2] = fmaxf(v.z + sb1[q*4+2], 0.f);
        h[q*4+3] = fmaxf(v.w + sb1[q*4+3], 0.f);
    }

    #pragma unroll
    for (int cc = 0; cc < NC; cc += 8) {
        float acc[8];
        #pragma unroll
        for (int j = 0; j < 8; j++) acc[j] = 0.f;
        #pragma unroll 8
        for (int k = 0; k < DH; k++) {
            float hk = h[k];
            const float4* wv = (const float4*)&sW2[k*NC + cc];
            float4 w0 = wv[0], w1 = wv[1];
            acc[0] += hk * w0.x; acc[1] += hk * w0.y;
            acc[2] += hk * w0.z; acc[3] += hk * w0.w;
            acc[4] += hk * w1.x; acc[5] += hk * w1.y;
            acc[6] += hk * w1.z; acc[7] += hk * w1.w;
        }
        __half2* dst = &g_h2h[(size_t)row*(NC/2) + cc/2];
        dst[0] = __floats2half2_rn(acc[0], acc[1]);
        dst[1] = __floats2half2_rn(acc[2], acc[3]);
        dst[2] = __floats2half2_rn(acc[4], acc[5]);
        dst[3] = __floats2half2_rn(acc[6], acc[7]);
    }
}

// ---------------- CSR aggregation layer 2 + bias + log_softmax --------------
__global__ void k_agg2_softmax(const float* __restrict__ b2,
                               float* __restrict__ out) {
    int warp = (blockIdx.x*blockDim.x + threadIdx.x) >> 5;
    if (warp >= NN) return;
    int lane = threadIdx.x & 31;
    bool act = lane < (NC/2);

    int start = g_rowptr[warp];
    int end   = g_rowptr[warp+1];
    float s = g_dinv[warp]; s *= s;

    float a0 = 0.f, a1 = 0.f;
    if (act) {
        float2 self = __half22float2(g_h2h[(size_t)warp*(NC/2) + lane]);
        a0 = s*self.x; a1 = s*self.y;
    }

    int2 eb = (start + lane < end) ? g_edge[start + lane] : make_int2(0, 0);
    for (int base = start; base < end; base += 32) {
        int n = min(32, end - base);
        int2 ebn = (base + 32 + lane < end) ? g_edge[base + 32 + lane]
                                            : make_int2(0, 0);
        #pragma unroll 8
        for (int j = 0; j < n; j++) {
            int   s2 = __shfl_sync(FULL, eb.x, j);
            float wj = __int_as_float(__shfl_sync(FULL, eb.y, j));
            if (act) {
                float2 hv = __half22float2(g_h2h[(size_t)s2*(NC/2) + lane]);
                a0 += wj * hv.x;
                a1 += wj * hv.y;
            }
        }
        eb = ebn;
    }

    if (act) {
        a0 += b2[lane*2];
        a1 += b2[lane*2 + 1];
    }

    float m = act ? fmaxf(a0, a1) : -1e30f;
    #pragma unroll
    for (int off = 16; off > 0; off >>= 1)
        m = fmaxf(m, __shfl_xor_sync(FULL, m, off));

    float es = act ? (expf(a0 - m) + expf(a1 - m)) : 0.f;
    #pragma unroll
    for (int off = 16; off > 0; off >>= 1)
        es += __shfl_xor_sync(FULL, es, off);

    float lse = m + logf(es);

    if (act) {
        *(float2*)&out[(size_t)warp*NC + lane*2] = make_float2(a0 - lse, a1 - lse);
    }
}

extern "C" void kernel_launch(void* const* d_in, const int* in_sizes, int n_in,
                              void* d_out, int out_size) {
    const float* x  = (const float*)d_in[0];
    const void*  ei = d_in[1];
    const float* ew = (const float*)d_in[2];
    const float* W1 = (const float*)d_in[3];
    const float* b1 = (const float*)d_in[4];
    const float* W2 = (const float*)d_in[5];
    const float* b2 = (const float*)d_in[6];
    float* out = (float*)d_out;

    cudaFuncSetAttribute(k_gemm1_tf32, cudaFuncAttributeMaxDynamicSharedMemorySize, SM_TOT);

    int warpGrid = (NN*32 + 255) / 256;

    // NOTE: launch index 3 is what ncu captures — gemm1 placed there.
    k_init         <<<(NN+255)/256, 256>>>((const int*)ei);
    k_transW       <<<(DF*DH+255)/256, 256>>>(W1);
    k_deg_hist     <<<(NE+255)/256, 256>>>(ei, ew);
    k_gemm1_tf32   <<<(NN+127)/128, 256, SM_TOT>>>(x);
    k_dinv         <<<(NN+255)/256, 256>>>();
    k_scan         <<<1, SCAN_T>>>();
    k_scatter      <<<(NE+255)/256, 256>>>(ei, ew);
    k_agg1         <<<warpGrid, 256>>>();
    k_relu_gemm2   <<<(NN+255)/256, 256>>>(b1, W2);
    k_agg2_softmax <<<warpGrid, 256>>>(b2, out);
}

// round 9
// speedup vs baseline: 2.1194x; 1.1296x over previous
#include <cuda_runtime.h>
#include <cuda_fp16.h>
#include <math.h>

#define NN 100000
#define NE 3200000
#define DF 512
#define DH 64
#define NC 40

#define FULL 0xffffffffu

// ---------------- scratch (device globals) ----------------------------------
__device__ int     g_is64;
__device__ float   g_deg[NN];
__device__ float   g_dinv[NN];
__device__ int     g_cnt[NN];
__device__ int     g_rowptr[NN+1];
__device__ int     g_cursor[NN];
__device__ int2    g_edge[NE];
__device__ __half2 g_h1h[(size_t)NN*(DH/2)];   // h1 as fp16 pairs
__device__ float   g_agg1[(size_t)NN*DH];
__device__ __half2 g_h2h[(size_t)NN*(NC/2)];   // h2 as fp16 pairs
__device__ float   g_BT[DH*DF];                // W1^T fp32  [n][k]

// ---------------- helpers -----------------------------------------------------
__device__ __forceinline__ unsigned smem_u32(const void* p) {
    unsigned a;
    asm("{ .reg .u64 t; cvta.to.shared.u64 t, %1; cvt.u32.u64 %0, t; }"
        : "=r"(a) : "l"(p));
    return a;
}

__device__ __forceinline__ unsigned to_tf32(float v) {
    unsigned r;
    asm("cvt.rna.tf32.f32 %0, %1;" : "=r"(r) : "f"(v));
    return r;
}

__device__ __forceinline__ void mma_tf32(float* d, const unsigned* a, const unsigned* b) {
    asm volatile("mma.sync.aligned.m16n8k8.row.col.f32.tf32.tf32.f32 "
        "{%0,%1,%2,%3}, {%4,%5,%6,%7}, {%8,%9}, {%0,%1,%2,%3};"
        : "+f"(d[0]), "+f"(d[1]), "+f"(d[2]), "+f"(d[3])
        : "r"(a[0]), "r"(a[1]), "r"(a[2]), "r"(a[3]), "r"(b[0]), "r"(b[1]));
}

__device__ __forceinline__ void cp16(unsigned dst, const void* src) {
    asm volatile("cp.async.cg.shared.global [%0], [%1], 16;"
                 :: "r"(dst), "l"(src) : "memory");
}

__device__ __forceinline__ int load_idx(const void* ei, size_t pos, int is64) {
    if (is64) return (int)((const long long*)ei)[pos];
    return ((const int*)ei)[pos];
}

// ---------------- init (+dtype detect in block 0) ---------------------------
__global__ void k_init(const int* __restrict__ ei32) {
    int i = blockIdx.x*blockDim.x + threadIdx.x;
    if (i < NN) { g_deg[i] = 1.0f; g_cnt[i] = 0; }
    if (blockIdx.x == 0) {
        __shared__ int nz;
        if (threadIdx.x == 0) nz = 0;
        __syncthreads();
        int local = 0;
        for (int s = threadIdx.x; s < 1024; s += blockDim.x)
            if (ei32[2*s + 1] != 0) local = 1;
        if (local) atomicOr(&nz, 1);
        __syncthreads();
        if (threadIdx.x == 0) g_is64 = (nz == 0) ? 1 : 0;
    }
}

__global__ void k_deg_hist(const void* __restrict__ ei,
                           const float* __restrict__ ew) {
    int e = blockIdx.x*blockDim.x + threadIdx.x;
    if (e >= NE) return;
    int is64 = g_is64;
    int c = load_idx(ei, (size_t)NE + e, is64);
    atomicAdd(&g_deg[c], ew[e]);
    atomicAdd(&g_cnt[c], 1);
}

__global__ void k_dinv() {
    int i = blockIdx.x*blockDim.x + threadIdx.x;
    if (i < NN) g_dinv[i] = rsqrtf(g_deg[i]);
}

// ---------------- W1 transpose (fp32) ---------------------------------------
__global__ void k_transW(const float* __restrict__ W1) {
    int idx = blockIdx.x*blockDim.x + threadIdx.x;
    if (idx >= DF*DH) return;
    int k = idx / DH, n = idx % DH;
    g_BT[n*DF + k] = W1[idx];
}

// ---------------- scan + scatter (CSR build) --------------------------------
#define SCAN_T 1024
#define CHUNK  98
__global__ void k_scan() {
    __shared__ int part[SCAN_T];
    int t = threadIdx.x;
    int lo = t * CHUNK;
    int hi = min(lo + CHUNK, NN);
    int sum = 0;
    for (int i = lo; i < hi; i++) sum += g_cnt[i];
    part[t] = sum;
    __syncthreads();
    #pragma unroll
    for (int off = 1; off < SCAN_T; off <<= 1) {
        int v = (t >= off) ? part[t-off] : 0;
        __syncthreads();
        part[t] += v;
        __syncthreads();
    }
    int run = (t > 0) ? part[t-1] : 0;
    for (int i = lo; i < hi; i++) {
        g_rowptr[i] = run;
        g_cursor[i] = run;
        run += g_cnt[i];
    }
    if (t == SCAN_T-1) g_rowptr[NN] = part[SCAN_T-1];
}

__global__ void k_scatter(const void* __restrict__ ei,
                          const float* __restrict__ ew) {
    int e = blockIdx.x*blockDim.x + threadIdx.x;
    if (e >= NE) return;
    int is64 = g_is64;
    int r = load_idx(ei, (size_t)e, is64);
    int c = load_idx(ei, (size_t)NE + e, is64);
    float w = g_dinv[r] * ew[e] * g_dinv[c];
    int pos = atomicAdd(&g_cursor[c], 1);
    g_edge[pos] = make_int2(r, __float_as_int(w));
}

// ---------------- GEMM1: single-pass TF32 mma.sync + cp.async dbuf ----------
// CTA: 256 thr (8 warps: warpM 0-3, warpN 0-1), tile M=128 N=64, K chunks of 64.
#define ASTR 68
#define AFL  (128*ASTR)
#define BFL  (64*ASTR)
#define SM_TOT ((2*AFL + 2*BFL)*4)

__global__ void __launch_bounds__(256) k_gemm1_tf32(const float* __restrict__ x) {
    extern __shared__ float smem[];
    unsigned sbase = smem_u32(smem);
    int tid = threadIdx.x;
    int wid = tid >> 5, lane = tid & 31;
    int warpM = wid >> 1, warpN = wid & 1;
    int g = lane >> 2, tig = lane & 3;
    int row0 = blockIdx.x * 128;

    int ar = tid >> 4, aq = tid & 15;
    int br = tid >> 4, bq = tid & 15;

    // prefetch chunk 0 into buffer 0
    {
        #pragma unroll
        for (int i = 0; i < 8; i++) {
            int r = ar + i*16;
            int grow = min(row0 + r, NN-1);
            cp16(sbase + (r*ASTR + aq*4)*4,
                 (const void*)&x[(size_t)grow*DF + aq*4]);
        }
        #pragma unroll
        for (int i = 0; i < 4; i++) {
            int r = br + i*16;
            cp16(sbase + (2*AFL + r*ASTR + bq*4)*4,
                 (const void*)&g_BT[(size_t)r*DF + bq*4]);
        }
        asm volatile("cp.async.commit_group;" ::: "memory");
    }

    float acc[2][4][4];
    #pragma unroll
    for (int mt = 0; mt < 2; mt++)
        #pragma unroll
        for (int nt = 0; nt < 4; nt++)
            #pragma unroll
            for (int q = 0; q < 4; q++) acc[mt][nt][q] = 0.f;

    for (int ch = 0; ch < 8; ch++) {
        int cur = ch & 1;
        if (ch < 7) {
            int nxt = (ch+1) & 1;
            int koff = (ch+1)*64;
            #pragma unroll
            for (int i = 0; i < 8; i++) {
                int r = ar + i*16;
                int grow = min(row0 + r, NN-1);
                cp16(sbase + (nxt*AFL + r*ASTR + aq*4)*4,
                     (const void*)&x[(size_t)grow*DF + koff + aq*4]);
            }
            #pragma unroll
            for (int i = 0; i < 4; i++) {
                int r = br + i*16;
                cp16(sbase + (2*AFL + nxt*BFL + r*ASTR + bq*4)*4,
                     (const void*)&g_BT[(size_t)r*DF + koff + bq*4]);
            }
            asm volatile("cp.async.commit_group;" ::: "memory");
            asm volatile("cp.async.wait_group 1;" ::: "memory");
        } else {
            asm volatile("cp.async.wait_group 0;" ::: "memory");
        }
        __syncthreads();

        const float* sA = smem + cur*AFL;
        const float* sB = smem + 2*AFL + cur*BFL;

        #pragma unroll
        for (int ks = 0; ks < 8; ks++) {
            int k0 = ks*8;
            unsigned aH[2][4], bH[4][2];
            #pragma unroll
            for (int mt = 0; mt < 2; mt++) {
                int rb = warpM*32 + mt*16;
                aH[mt][0] = to_tf32(sA[(rb+g  )*ASTR + k0+tig  ]);
                aH[mt][1] = to_tf32(sA[(rb+g+8)*ASTR + k0+tig  ]);
                aH[mt][2] = to_tf32(sA[(rb+g  )*ASTR + k0+tig+4]);
                aH[mt][3] = to_tf32(sA[(rb+g+8)*ASTR + k0+tig+4]);
            }
            #pragma unroll
            for (int nt = 0; nt < 4; nt++) {
                int n = warpN*32 + nt*8 + g;
                bH[nt][0] = to_tf32(sB[n*ASTR + k0+tig  ]);
                bH[nt][1] = to_tf32(sB[n*ASTR + k0+tig+4]);
            }
            #pragma unroll
            for (int mt = 0; mt < 2; mt++)
                #pragma unroll
                for (int nt = 0; nt < 4; nt++)
                    mma_tf32(acc[mt][nt], aH[mt], bH[nt]);
        }
        __syncthreads();
    }

    // epilogue: D frag (g, 2*tig) -> g_h1h (fp16 pairs)
    #pragma unroll
    for (int mt = 0; mt < 2; mt++) {
        #pragma unroll
        for (int half = 0; half < 2; half++) {
            int grow = row0 + warpM*32 + mt*16 + g + half*8;
            if (grow < NN) {
                __half2* dst = &g_h1h[(size_t)grow*(DH/2) + warpN*16 + tig];
                #pragma unroll
                for (int nt = 0; nt < 4; nt++)
                    dst[nt*4] = __floats2half2_rn(acc[mt][nt][half*2],
                                                  acc[mt][nt][half*2+1]);
            }
        }
    }
}

// ---------------- CSR aggregation layer 1 (fp16 gather, fp32 accum) ---------
__global__ void k_agg1() {
    int warp = (blockIdx.x*blockDim.x + threadIdx.x) >> 5;
    if (warp >= NN) return;
    int lane = threadIdx.x & 31;

    int start = g_rowptr[warp];
    int end   = g_rowptr[warp+1];
    float s = g_dinv[warp]; s *= s;

    float2 self = __half22float2(g_h1h[(size_t)warp*(DH/2) + lane]);
    float2 acc  = make_float2(s*self.x, s*self.y);

    int2 eb = (start + lane < end) ? g_edge[start + lane] : make_int2(0, 0);
    for (int base = start; base < end; base += 32) {
        int n = min(32, end - base);
        int2 ebn = (base + 32 + lane < end) ? g_edge[base + 32 + lane]
                                            : make_int2(0, 0);
        #pragma unroll 8
        for (int j = 0; j < n; j++) {
            int   s2 = __shfl_sync(FULL, eb.x, j);
            float wj = __int_as_float(__shfl_sync(FULL, eb.y, j));
            float2 hv = __half22float2(g_h1h[(size_t)s2*(DH/2) + lane]);
            acc.x += wj * hv.x;
            acc.y += wj * hv.y;
        }
        eb = ebn;
    }
    *(float2*)&g_agg1[(size_t)warp*DH + lane*2] = acc;
}

// ---------------- h2 = relu(agg1 + b1) @ W2  (fp16 output) ------------------
__global__ void k_relu_gemm2(const float* __restrict__ b1,
                             const float* __restrict__ W2) {
    __shared__ float sW2[DH*NC];
    __shared__ float sb1[DH];
    int tid = threadIdx.x;
    for (int i = tid; i < DH*NC; i += blockDim.x) sW2[i] = W2[i];
    if (tid < DH) sb1[tid] = b1[tid];
    __syncthreads();

    int row = blockIdx.x*blockDim.x + tid;
    if (row >= NN) return;

    float h[DH];
    const float4* av = (const float4*)&g_agg1[(size_t)row*DH];
    #pragma unroll
    for (int q = 0; q < DH/4; q++) {
        float4 v = av[q];
        h[q*4+0] = fmaxf(v.x + sb1[q*4+0], 0.f);
        h[q*4+1] = fmaxf(v.y + sb1[q*4+1], 0.f);
        h[q*4+2] = fmaxf(v.z + sb1[q*4+2], 0.f);
        h[q*4+3] = fmaxf(v.w + sb1[q*4+3], 0.f);
    }

    #pragma unroll
    for (int cc = 0; cc < NC; cc += 8) {
        float acc[8];
        #pragma unroll
        for (int j = 0; j < 8; j++) acc[j] = 0.f;
        #pragma unroll 8
        for (int k = 0; k < DH; k++) {
            float hk = h[k];
            const float4* wv = (const float4*)&sW2[k*NC + cc];
            float4 w0 = wv[0], w1 = wv[1];
            acc[0] += hk * w0.x; acc[1] += hk * w0.y;
            acc[2] += hk * w0.z; acc[3] += hk * w0.w;
            acc[4] += hk * w1.x; acc[5] += hk * w1.y;
            acc[6] += hk * w1.z; acc[7] += hk * w1.w;
        }
        __half2* dst = &g_h2h[(size_t)row*(NC/2) + cc/2];
        dst[0] = __floats2half2_rn(acc[0], acc[1]);
        dst[1] = __floats2half2_rn(acc[2], acc[3]);
        dst[2] = __floats2half2_rn(acc[4], acc[5]);
        dst[3] = __floats2half2_rn(acc[6], acc[7]);
    }
}

// ---------------- CSR aggregation layer 2 + bias + log_softmax --------------
__global__ void k_agg2_softmax(const float* __restrict__ b2,
                               float* __restrict__ out) {
    int warp = (blockIdx.x*blockDim.x + threadIdx.x) >> 5;
    if (warp >= NN) return;
    int lane = threadIdx.x & 31;
    bool act = lane < (NC/2);

    int start = g_rowptr[warp];
    int end   = g_rowptr[warp+1];
    float s = g_dinv[warp]; s *= s;

    float a0 = 0.f, a1 = 0.f;
    if (act) {
        float2 self = __half22float2(g_h2h[(size_t)warp*(NC/2) + lane]);
        a0 = s*self.x; a1 = s*self.y;
    }

    int2 eb = (start + lane < end) ? g_edge[start + lane] : make_int2(0, 0);
    for (int base = start; base < end; base += 32) {
        int n = min(32, end - base);
        int2 ebn = (base + 32 + lane < end) ? g_edge[base + 32 + lane]
                                            : make_int2(0, 0);
        #pragma unroll 8
        for (int j = 0; j < n; j++) {
            int   s2 = __shfl_sync(FULL, eb.x, j);
            float wj = __int_as_float(__shfl_sync(FULL, eb.y, j));
            if (act) {
                float2 hv = __half22float2(g_h2h[(size_t)s2*(NC/2) + lane]);
                a0 += wj * hv.x;
                a1 += wj * hv.y;
            }
        }
        eb = ebn;
    }

    if (act) {
        a0 += b2[lane*2];
        a1 += b2[lane*2 + 1];
    }

    float m = act ? fmaxf(a0, a1) : -1e30f;
    #pragma unroll
    for (int off = 16; off > 0; off >>= 1)
        m = fmaxf(m, __shfl_xor_sync(FULL, m, off));

    float es = act ? (expf(a0 - m) + expf(a1 - m)) : 0.f;
    #pragma unroll
    for (int off = 16; off > 0; off >>= 1)
        es += __shfl_xor_sync(FULL, es, off);

    float lse = m + logf(es);

    if (act) {
        *(float2*)&out[(size_t)warp*NC + lane*2] = make_float2(a0 - lse, a1 - lse);
    }
}

extern "C" void kernel_launch(void* const* d_in, const int* in_sizes, int n_in,
                              void* d_out, int out_size) {
    const float* x  = (const float*)d_in[0];
    const void*  ei = d_in[1];
    const float* ew = (const float*)d_in[2];
    const float* W1 = (const float*)d_in[3];
    const float* b1 = (const float*)d_in[4];
    const float* W2 = (const float*)d_in[5];
    const float* b2 = (const float*)d_in[6];
    float* out = (float*)d_out;

    cudaFuncSetAttribute(k_gemm1_tf32, cudaFuncAttributeMaxDynamicSharedMemorySize, SM_TOT);

    int warpGrid = (NN*32 + 255) / 256;

    // launch index 3 is what ncu captures — gemm1 kept there to verify.
    k_init         <<<(NN+255)/256, 256>>>((const int*)ei);
    k_transW       <<<(DF*DH+255)/256, 256>>>(W1);
    k_deg_hist     <<<(NE+255)/256, 256>>>(ei, ew);
    k_gemm1_tf32   <<<(NN+127)/128, 256, SM_TOT>>>(x);
    k_dinv         <<<(NN+255)/256, 256>>>();
    k_scan         <<<1, SCAN_T>>>();
    k_scatter      <<<(NE+255)/256, 256>>>(ei, ew);
    k_agg1         <<<warpGrid, 256>>>();
    k_relu_gemm2   <<<(NN+255)/256, 256>>>(b1, W2);
    k_agg2_softmax <<<warpGrid, 256>>>(b2, out);
}